// round 7
// baseline (speedup 1.0000x reference)
#include <cuda_runtime.h>
#include <cuda_bf16.h>

// ConformerAttention: B=8, S=1024, D=512, H=8, hd=64, P=2047
// rel_shift identity: shifted[i,j] = raw[i, j + (S-1) - i] -> p row r = 1023 + j - i.

#define CB 8
#define CS 1024
#define CD 512
#define CH 8
#define CHD 64
#define CP 2047
#define MTOK (CB*CS)   // 8192

typedef __nv_bfloat16 bf16;
typedef __nv_bfloat162 bf162;

__device__ __forceinline__ unsigned pack_bf2(float lo, float hi) {
    unsigned r; asm("cvt.rn.bf16x2.f32 %0, %1, %2;" : "=r"(r) : "f"(hi), "f"(lo)); return r;
}
__device__ __forceinline__ void mma16(float4& c, unsigned a0, unsigned a1, unsigned a2, unsigned a3,
                                      unsigned b0, unsigned b1) {
    asm volatile(
        "mma.sync.aligned.m16n8k16.row.col.f32.bf16.bf16.f32 "
        "{%0,%1,%2,%3}, {%4,%5,%6,%7}, {%8,%9}, {%0,%1,%2,%3};"
        : "+f"(c.x), "+f"(c.y), "+f"(c.z), "+f"(c.w)
        : "r"(a0), "r"(a1), "r"(a2), "r"(a3), "r"(b0), "r"(b1));
}
__device__ __forceinline__ unsigned sptr(const void* p) {
    return (unsigned)__cvta_generic_to_shared(p);
}
__device__ __forceinline__ void ldsm_x4(unsigned* r, unsigned addr) {
    asm volatile("ldmatrix.sync.aligned.m8n8.x4.shared.b16 {%0,%1,%2,%3}, [%4];"
        : "=r"(r[0]), "=r"(r[1]), "=r"(r[2]), "=r"(r[3]) : "r"(addr));
}
__device__ __forceinline__ void ldsm_x2(unsigned& r0, unsigned& r1, unsigned addr) {
    asm volatile("ldmatrix.sync.aligned.m8n8.x2.shared.b16 {%0,%1}, [%2];"
        : "=r"(r0), "=r"(r1) : "r"(addr));
}

// -------- scratch (allocation-free: device globals) --------
__device__ bf16 g_h [MTOK*CD];
__device__ bf16 g_q [CB*CH*CS*CHD];      // [bh][S][hd]
__device__ bf16 g_k [CB*CH*CS*CHD];      // [bh][S][hd]
__device__ bf16 g_v [CB*CH*CS*CHD];      // [bh][hd][S]  (pre-transposed, mode 5)
__device__ bf16 g_p [CH*CP*CHD];         // [H][P][hd]
__device__ bf16 g_ao[MTOK*CD];           // [B,S,D]

// ============================ LayerNorm (fp32 in -> bf16 out) ============================
__global__ void __launch_bounds__(128) ln_kernel(const float* __restrict__ x,
    const float* __restrict__ w, const float* __restrict__ b, bf16* __restrict__ out)
{
    int row = blockIdx.x;
    int t = threadIdx.x;
    const float* xr = x + (size_t)row * CD;
    float4 v = *(const float4*)(xr + t * 4);
    float s = v.x + v.y + v.z + v.w;
    #pragma unroll
    for (int o = 16; o; o >>= 1) s += __shfl_xor_sync(0xffffffffu, s, o);
    __shared__ float ws1[4], ws2[4];
    if ((t & 31) == 0) ws1[t >> 5] = s;
    __syncthreads();
    float mean = (ws1[0] + ws1[1] + ws1[2] + ws1[3]) * (1.0f / 512.0f);
    float dx = v.x - mean, dy = v.y - mean, dz = v.z - mean, dw = v.w - mean;
    float q = dx*dx + dy*dy + dz*dz + dw*dw;
    #pragma unroll
    for (int o = 16; o; o >>= 1) q += __shfl_xor_sync(0xffffffffu, q, o);
    if ((t & 31) == 0) ws2[t >> 5] = q;
    __syncthreads();
    float var = (ws2[0] + ws2[1] + ws2[2] + ws2[3]) * (1.0f / 512.0f);
    float rstd = rsqrtf(var + 1e-5f);
    float4 wv = *(const float4*)(w + t * 4);
    float4 bv = *(const float4*)(b + t * 4);
    float ox = dx * rstd * wv.x + bv.x;
    float oy = dy * rstd * wv.y + bv.y;
    float oz = dz * rstd * wv.z + bv.z;
    float ow = dw * rstd * wv.w + bv.w;
    *(uint2*)(out + (size_t)row * CD + t * 4) = make_uint2(pack_bf2(ox, oy), pack_bf2(oz, ow));
}

// ============================ GEMM core: C = A @ W^T (bf16 mma + ldmatrix) ============================
__device__ __forceinline__ void gemm_core(
    const void* __restrict__ Ap, int M, int a_bf16,
    const float* __restrict__ W,
    const float* __restrict__ bias,
    const float* __restrict__ resid,
    void* __restrict__ outp, int mode,
    bf16* As, bf16* Ws)
{
    const int tid = threadIdx.x;
    const int l = tid & 31, wid = tid >> 5;
    const int wm = wid >> 1, wn = wid & 1;
    const int m0 = blockIdx.y * 128, n0 = blockIdx.x * 128;
    const int gid = l >> 2, tig = l & 3;
    const int lr = l & 7;
    const int a_row = ((l >> 3) & 1) * 8 + lr;
    const int a_col = (l >> 4) * 8;
    const int b_col = ((l >> 3) & 1) * 8;

    float4 cacc[2][8];
    #pragma unroll
    for (int mt = 0; mt < 2; mt++)
        #pragma unroll
        for (int nt = 0; nt < 8; nt++) cacc[mt][nt] = make_float4(0.f, 0.f, 0.f, 0.f);

    const unsigned aA = sptr(As) + ((wm * 32 + a_row) * 72 + a_col) * 2;
    const unsigned aB = sptr(Ws) + ((wn * 64 + lr) * 72 + b_col) * 2;

    for (int k0 = 0; k0 < 512; k0 += 64) {
        __syncthreads();
        #pragma unroll
        for (int it = 0; it < 4; it++) {
            int idx = tid + it * 256;
            int row = idx >> 3, seg = idx & 7;
            int kk = k0 + seg * 8;
            int am = m0 + row;
            uint4 aw = make_uint4(0, 0, 0, 0);
            if (am < M) {
                if (a_bf16) {
                    aw = *(const uint4*)((const bf16*)Ap + (size_t)am * 512 + kk);
                } else {
                    const float* ar = (const float*)Ap + (size_t)am * 512 + kk;
                    float4 f0 = *(const float4*)ar;
                    float4 f1 = *(const float4*)(ar + 4);
                    aw = make_uint4(pack_bf2(f0.x, f0.y), pack_bf2(f0.z, f0.w),
                                    pack_bf2(f1.x, f1.y), pack_bf2(f1.z, f1.w));
                }
            }
            *(uint4*)&As[row * 72 + seg * 8] = aw;
            const float* wr = W + (size_t)(n0 + row) * 512 + kk;
            float4 w0 = *(const float4*)wr;
            float4 w1 = *(const float4*)(wr + 4);
            *(uint4*)&Ws[row * 72 + seg * 8] =
                make_uint4(pack_bf2(w0.x, w0.y), pack_bf2(w0.z, w0.w),
                           pack_bf2(w1.x, w1.y), pack_bf2(w1.z, w1.w));
        }
        __syncthreads();
        #pragma unroll
        for (int ks = 0; ks < 4; ks++) {
            unsigned a0[4], a1[4];
            ldsm_x4(a0, aA + ks * 32);
            ldsm_x4(a1, aA + 16 * 144 + ks * 32);
            #pragma unroll
            for (int nt = 0; nt < 8; nt++) {
                unsigned b0, b1;
                ldsm_x2(b0, b1, aB + nt * 8 * 144 + ks * 32);
                mma16(cacc[0][nt], a0[0], a0[1], a0[2], a0[3], b0, b1);
                mma16(cacc[1][nt], a1[0], a1[1], a1[2], a1[3], b0, b1);
            }
        }
    }

    #pragma unroll
    for (int mt = 0; mt < 2; mt++) {
        #pragma unroll
        for (int nt = 0; nt < 8; nt++) {
            float4 c = cacc[mt][nt];
            int r0 = m0 + wm * 32 + mt * 16 + gid;
            int c0 = n0 + wn * 64 + nt * 8 + tig * 2;
            float vals[4] = {c.x, c.y, c.z, c.w};
            #pragma unroll
            for (int e = 0; e < 4; e++) {
                int m = r0 + (e >= 2 ? 8 : 0);
                int n = c0 + (e & 1);
                float val = vals[e];
                if (mode == 0) {
                    int bi = m >> 10, sr = m & 1023;
                    ((bf16*)outp)[((size_t)(bi * CH + (n >> 6)) << 16) + ((size_t)sr << 6) + (n & 63)]
                        = __float2bfloat16(val + bias[n]);
                } else if (mode == 5) {
                    int bi = m >> 10, sr = m & 1023;
                    ((bf16*)outp)[((size_t)(bi * CH + (n >> 6)) << 16) + (size_t)(n & 63) * 1024 + sr]
                        = __float2bfloat16(val + bias[n]);
                } else if (mode == 3) {
                    if (m < M)
                        ((bf16*)outp)[((size_t)(n >> 6) * CP + m) * 64 + (n & 63)]
                            = __float2bfloat16(val);
                } else {
                    size_t idx = (size_t)m * 512 + n;
                    ((float*)outp)[idx] = val + bias[n] + resid[idx];
                }
            }
        }
    }
}

__global__ void __launch_bounds__(256, 2) gemm_kernel(
    const void* __restrict__ Ap, int M, int a_bf16,
    const float* __restrict__ W, const float* __restrict__ bias,
    const float* __restrict__ resid, void* __restrict__ outp, int mode)
{
    __shared__ bf16 As[128 * 72];
    __shared__ bf16 Ws[128 * 72];
    gemm_core(Ap, M, a_bf16, W, bias, resid, outp, mode, As, Ws);
}

__global__ void __launch_bounds__(256, 2) qkv_kernel(
    const bf16* __restrict__ A,
    const float* __restrict__ Wq, const float* __restrict__ Wk, const float* __restrict__ Wv,
    const float* __restrict__ bq, const float* __restrict__ bk, const float* __restrict__ bv,
    bf16* __restrict__ q, bf16* __restrict__ k, bf16* __restrict__ v)
{
    __shared__ bf16 As[128 * 72];
    __shared__ bf16 Ws[128 * 72];
    int z = blockIdx.z;
    const float* W    = (z == 0) ? Wq : (z == 1) ? Wk : Wv;
    const float* bias = (z == 0) ? bq : (z == 1) ? bk : bv;
    bf16* o           = (z == 0) ? q  : (z == 1) ? k  : v;
    gemm_core(A, MTOK, 1, W, bias, nullptr, o, (z == 2) ? 5 : 0, As, Ws);
}

// ============================ Fused attention (bf16 mma + ldmatrix, 256 threads) ============================
constexpr int SC_STR = 1060;
constexpr int SC_F   = 32 * SC_STR;            // fp32 scores (AV partials overlay at end)
constexpr int QT_E   = 32 * 72;                // bf16 q tiles
constexpr int KB_E   = 256 * 72;               // bf16 K/P chunk (Vt 64*264=16896 fits)
constexpr int ASM_B  = SC_F * 4 + 2 * QT_E * 2 + KB_E * 2;   // 181,760 bytes

__global__ void __launch_bounds__(256, 1) attn_kernel(const float* __restrict__ bu,
    const float* __restrict__ bvp, bf16* __restrict__ ao)
{
    extern __shared__ float sm[];
    float* sc  = sm;                                   // [32][1060] fp32
    bf16* qut  = (bf16*)(sm + SC_F);                   // [32][72]
    bf16* qvt  = qut + QT_E;                           // [32][72]
    bf16* kbuf = qvt + QT_E;                           // [256][72] / Vt [64][264]

    const int tid = threadIdx.x;
    const int w = tid >> 5, l = tid & 31;
    const int gid = l >> 2, tig = l & 3;
    const int lr = l & 7;
    const int a_row = ((l >> 3) & 1) * 8 + lr;
    const int a_col = (l >> 4) * 8;
    const int b_col = ((l >> 3) & 1) * 8;
    const int qt = blockIdx.x & 31;
    const int bh = blockIdx.x >> 5;
    const int h  = bh & 7, b = bh >> 3;
    const int i0 = qt * 32;
    const bf16* qbase = g_q + (size_t)bh * (CS * CHD);
    const bf16* kbase = g_k + (size_t)bh * (CS * CHD);
    const bf16* vbase = g_v + (size_t)bh * (CS * CHD);   // [64][1024]
    const bf16* pbase = g_p + (size_t)h  * (CP * CHD);

    // ---- Phase A: q tile [32][72] bf16, both bias variants ----
    {
        int ii = tid >> 3, dq = (tid & 7) * 8;
        uint4 qw = *(const uint4*)(qbase + (size_t)(i0 + ii) * 64 + dq);
        unsigned wsv[4] = {qw.x, qw.y, qw.z, qw.w};
        unsigned uo[4], vo[4];
        #pragma unroll
        for (int j = 0; j < 4; j++) {
            float2 f = __bfloat1622float2(*(bf162*)&wsv[j]);
            int d = dq + 2 * j;
            uo[j] = pack_bf2(f.x + bu [h*64+d], f.y + bu [h*64+d+1]);
            vo[j] = pack_bf2(f.x + bvp[h*64+d], f.y + bvp[h*64+d+1]);
        }
        *(uint4*)&qut[ii * 72 + dq] = make_uint4(uo[0], uo[1], uo[2], uo[3]);
        *(uint4*)&qvt[ii * 72 + dq] = make_uint4(vo[0], vo[1], vo[2], vo[3]);
    }

    const unsigned aQU = sptr(qut) + (a_row * 72 + a_col) * 2;
    const unsigned aQV = sptr(qvt) + (a_row * 72 + a_col) * 2;
    const unsigned aKB = sptr(kbuf) + ((w * 16 + lr) * 72 + b_col) * 2;
    const int rlo = 992 - i0;

    // ======== Phase B1: pos scores over band (5 chunks of 256), sheared assign ========
    #pragma unroll 1
    for (int ch = 0; ch < 5; ch++) {
        int rbase = rlo + ch * 256;
        __syncthreads();
        #pragma unroll
        for (int it = 0; it < 8; it++) {
            int idx = tid + it * 256;
            int row = idx >> 3, seg = idx & 7;
            int r = rbase + row;
            uint4 v = (r <= 2046) ? *(const uint4*)(pbase + (size_t)r * 64 + seg * 8)
                                  : make_uint4(0, 0, 0, 0);
            *(uint4*)&kbuf[row * 72 + seg * 8] = v;
        }
        __syncthreads();
        float4 cacc[2][2][2];   // [s][mt][nt]
        #pragma unroll
        for (int s = 0; s < 2; s++)
            #pragma unroll
            for (int mt = 0; mt < 2; mt++)
                #pragma unroll
                for (int nt = 0; nt < 2; nt++) cacc[s][mt][nt] = make_float4(0.f,0.f,0.f,0.f);
        #pragma unroll
        for (int ks = 0; ks < 4; ks++) {
            unsigned a0[4], a1[4];
            ldsm_x4(a0, aQV + ks * 32);
            ldsm_x4(a1, aQV + 16 * 144 + ks * 32);
            #pragma unroll
            for (int s = 0; s < 2; s++) {
                #pragma unroll
                for (int nt = 0; nt < 2; nt++) {
                    unsigned b0, b1;
                    ldsm_x2(b0, b1, aKB + (s * 128 + nt * 8) * 144 + ks * 32);
                    mma16(cacc[s][0][nt], a0[0], a0[1], a0[2], a0[3], b0, b1);
                    mma16(cacc[s][1][nt], a1[0], a1[1], a1[2], a1[3], b0, b1);
                }
            }
        }
        #pragma unroll
        for (int s = 0; s < 2; s++) {
            #pragma unroll
            for (int mt = 0; mt < 2; mt++) {
                #pragma unroll
                for (int nt = 0; nt < 2; nt++) {
                    float4 c = cacc[s][mt][nt];
                    int ii = mt * 16 + gid;
                    int rr = ch * 256 + s * 128 + w * 16 + nt * 8 + tig * 2;
                    int jx = rr + ii - 31;
                    if (jx >= 0 && jx < 1024)         sc[ii * SC_STR + jx]     = c.x;
                    if (jx + 1 >= 0 && jx + 1 < 1024) sc[ii * SC_STR + jx + 1] = c.y;
                    int jz = jx + 8, i2 = ii + 8;
                    if (jz >= 0 && jz < 1024)         sc[i2 * SC_STR + jz]     = c.z;
                    if (jz + 1 >= 0 && jz + 1 < 1024) sc[i2 * SC_STR + jz + 1] = c.w;
                }
            }
        }
    }

    // ======== Phase B2: content scores (4 chunks of 256), add in place ========
    #pragma unroll 1
    for (int ch = 0; ch < 4; ch++) {
        __syncthreads();
        #pragma unroll
        for (int it = 0; it < 8; it++) {
            int idx = tid + it * 256;
            int row = idx >> 3, seg = idx & 7;
            *(uint4*)&kbuf[row * 72 + seg * 8] =
                *(const uint4*)(kbase + (size_t)(ch * 256 + row) * 64 + seg * 8);
        }
        __syncthreads();
        float4 cacc[2][2][2];
        #pragma unroll
        for (int s = 0; s < 2; s++)
            #pragma unroll
            for (int mt = 0; mt < 2; mt++)
                #pragma unroll
                for (int nt = 0; nt < 2; nt++) cacc[s][mt][nt] = make_float4(0.f,0.f,0.f,0.f);
        #pragma unroll
        for (int ks = 0; ks < 4; ks++) {
            unsigned a0[4], a1[4];
            ldsm_x4(a0, aQU + ks * 32);
            ldsm_x4(a1, aQU + 16 * 144 + ks * 32);
            #pragma unroll
            for (int s = 0; s < 2; s++) {
                #pragma unroll
                for (int nt = 0; nt < 2; nt++) {
                    unsigned b0, b1;
                    ldsm_x2(b0, b1, aKB + (s * 128 + nt * 8) * 144 + ks * 32);
                    mma16(cacc[s][0][nt], a0[0], a0[1], a0[2], a0[3], b0, b1);
                    mma16(cacc[s][1][nt], a1[0], a1[1], a1[2], a1[3], b0, b1);
                }
            }
        }
        #pragma unroll
        for (int s = 0; s < 2; s++) {
            #pragma unroll
            for (int mt = 0; mt < 2; mt++) {
                #pragma unroll
                for (int nt = 0; nt < 2; nt++) {
                    float4 c = cacc[s][mt][nt];
                    int ii = mt * 16 + gid;
                    int col = ch * 256 + s * 128 + w * 16 + nt * 8 + tig * 2;
                    sc[ii * SC_STR + col]           += c.x;
                    sc[ii * SC_STR + col + 1]       += c.y;
                    sc[(ii + 8) * SC_STR + col]     += c.z;
                    sc[(ii + 8) * SC_STR + col + 1] += c.w;
                }
            }
        }
    }
    __syncthreads();

    // ======== Phase C: softmax (scale 1/8 inside exp), 4 rows per warp ========
    #pragma unroll
    for (int rr = 0; rr < 4; rr++) {
        int row = w * 4 + rr;
        float* rp = sc + row * SC_STR;
        float4 vv[8];
        float mx = -1e30f;
        #pragma unroll
        for (int g = 0; g < 8; g++) {
            vv[g] = *(const float4*)&rp[g * 128 + l * 4];
            mx = fmaxf(mx, fmaxf(fmaxf(vv[g].x, vv[g].y), fmaxf(vv[g].z, vv[g].w)));
        }
        #pragma unroll
        for (int o = 16; o; o >>= 1) mx = fmaxf(mx, __shfl_xor_sync(0xffffffffu, mx, o));
        float sum = 0.f;
        #pragma unroll
        for (int g = 0; g < 8; g++) {
            vv[g].x = __expf((vv[g].x - mx) * 0.125f);
            vv[g].y = __expf((vv[g].y - mx) * 0.125f);
            vv[g].z = __expf((vv[g].z - mx) * 0.125f);
            vv[g].w = __expf((vv[g].w - mx) * 0.125f);
            sum += vv[g].x + vv[g].y + vv[g].z + vv[g].w;
        }
        #pragma unroll
        for (int o = 16; o; o >>= 1) sum += __shfl_xor_sync(0xffffffffu, sum, o);
        float inv = 1.0f / sum;
        #pragma unroll
        for (int g = 0; g < 8; g++) {
            vv[g].x *= inv; vv[g].y *= inv; vv[g].z *= inv; vv[g].w *= inv;
            *(float4*)&rp[g * 128 + l * 4] = vv[g];
        }
    }

    // ======== Phase D: O = attn @ V (4 chunks of 256 keys), 8-way k-split ========
    bf16* Vt = kbuf;                                   // [64][264]
    float4 oacc[2][8];
    #pragma unroll
    for (int mt = 0; mt < 2; mt++)
        #pragma unroll
        for (int nt = 0; nt < 8; nt++) oacc[mt][nt] = make_float4(0.f,0.f,0.f,0.f);

    #pragma unroll 1
    for (int ch = 0; ch < 4; ch++) {
        __syncthreads();
        #pragma unroll
        for (int it = 0; it < 8; it++) {
            int idx = tid + it * 256;
            int d = idx >> 5, seg = idx & 31;
            *(uint4*)&Vt[d * 264 + seg * 8] =
                *(const uint4*)(vbase + (size_t)d * 1024 + ch * 256 + seg * 8);
        }
        __syncthreads();
        #pragma unroll
        for (int ks = 0; ks < 2; ks++) {
            int klocal = w * 32 + ks * 16;
            int kg = ch * 256 + klocal + 2 * tig;
            unsigned a[2][4];
            #pragma unroll
            for (int mt = 0; mt < 2; mt++) {
                const float* s0 = sc + (mt * 16 + gid) * SC_STR + kg;
                const float* s1 = s0 + 8 * SC_STR;
                float2 u;
                u = *(const float2*)s0;       a[mt][0] = pack_bf2(u.x, u.y);
                u = *(const float2*)s1;       a[mt][1] = pack_bf2(u.x, u.y);
                u = *(const float2*)(s0 + 8); a[mt][2] = pack_bf2(u.x, u.y);
                u = *(const float2*)(s1 + 8); a[mt][3] = pack_bf2(u.x, u.y);
            }
            #pragma unroll
            for (int nt = 0; nt < 8; nt++) {
                unsigned b0, b1;
                ldsm_x2(b0, b1, sptr(Vt) + ((nt * 8 + lr) * 264 + b_col + klocal) * 2);
                mma16(oacc[0][nt], a[0][0], a[0][1], a[0][2], a[0][3], b0, b1);
                mma16(oacc[1][nt], a[1][0], a[1][1], a[1][2], a[1][3], b0, b1);
            }
        }
    }

    // per-warp partials -> sc overlay (probs dead), then cross-warp reduce
    __syncthreads();
    {
        float* pb = sc + w * 2176;
        #pragma unroll
        for (int mt = 0; mt < 2; mt++) {
            #pragma unroll
            for (int nt = 0; nt < 8; nt++) {
                float4 c = oacc[mt][nt];
                int r = mt * 16 + gid;
                int cc = nt * 8 + tig * 2;
                pb[r * 68 + cc]           = c.x;
                pb[r * 68 + cc + 1]       = c.y;
                pb[(r + 8) * 68 + cc]     = c.z;
                pb[(r + 8) * 68 + cc + 1] = c.w;
            }
        }
    }
    __syncthreads();
    #pragma unroll
    for (int rep = 0; rep < 2; rep++) {
        int e = tid + rep * 256;
        int row = e >> 4, d4 = (e & 15) * 4;
        float4 s = make_float4(0.f, 0.f, 0.f, 0.f);
        #pragma unroll
        for (int ww = 0; ww < 8; ww++) {
            float4 p4 = *(const float4*)&sc[ww * 2176 + row * 68 + d4];
            s.x += p4.x; s.y += p4.y; s.z += p4.z; s.w += p4.w;
        }
        *(uint2*)(ao + (size_t)(b * 1024 + i0 + row) * 512 + h * 64 + d4)
            = make_uint2(pack_bf2(s.x, s.y), pack_bf2(s.z, s.w));
    }
}

// ============================ launch ============================
extern "C" void kernel_launch(void* const* d_in, const int* in_sizes, int n_in,
                              void* d_out, int out_size)
{
    const float* x       = (const float*)d_in[0];
    const float* pos_emb = (const float*)d_in[1];
    const float* ln_w    = (const float*)d_in[2];
    const float* ln_b    = (const float*)d_in[3];
    const float* Wq      = (const float*)d_in[4];
    const float* bq      = (const float*)d_in[5];
    const float* Wk      = (const float*)d_in[6];
    const float* bk      = (const float*)d_in[7];
    const float* Wv      = (const float*)d_in[8];
    const float* bv      = (const float*)d_in[9];
    const float* Wo      = (const float*)d_in[10];
    const float* bo      = (const float*)d_in[11];
    const float* Wp      = (const float*)d_in[12];
    const float* pbu     = (const float*)d_in[13];
    const float* pbv     = (const float*)d_in[14];
    float* out = (float*)d_out;

    bf16 *hp, *qp, *kp, *vp, *pp, *aop;
    cudaGetSymbolAddress((void**)&hp,  g_h);
    cudaGetSymbolAddress((void**)&qp,  g_q);
    cudaGetSymbolAddress((void**)&kp,  g_k);
    cudaGetSymbolAddress((void**)&vp,  g_v);
    cudaGetSymbolAddress((void**)&pp,  g_p);
    cudaGetSymbolAddress((void**)&aop, g_ao);

    cudaFuncSetAttribute(attn_kernel, cudaFuncAttributeMaxDynamicSharedMemorySize, ASM_B);

    ln_kernel<<<MTOK, 128>>>(x, ln_w, ln_b, hp);

    qkv_kernel<<<dim3(4, 64, 3), 256>>>(hp, Wq, Wk, Wv, bq, bk, bv, qp, kp, vp);
    gemm_kernel<<<dim3(4, 16), 256>>>(pos_emb, CP, 0, Wp, nullptr, nullptr, pp, 3);

    attn_kernel<<<CB * CH * (CS / 32), 256, ASM_B>>>(pbu, pbv, aop);

    gemm_kernel<<<dim3(4, 64), 256>>>(aop, MTOK, 1, Wo, bo, x, out, 4);
}

// round 8
// speedup vs baseline: 1.8049x; 1.8049x over previous
#include <cuda_runtime.h>
#include <cuda_bf16.h>

// ConformerAttention: B=8, S=1024, D=512, H=8, hd=64, P=2047
// rel_shift identity: shifted[i,j] = raw[i, j + (S-1) - i] -> p row r = 1023 + j - i.

#define CB 8
#define CS 1024
#define CD 512
#define CH 8
#define CHD 64
#define CP 2047
#define MTOK (CB*CS)   // 8192

typedef __nv_bfloat16 bf16;
typedef __nv_bfloat162 bf162;

__device__ __forceinline__ unsigned pack_bf2(float lo, float hi) {
    unsigned r; asm("cvt.rn.bf16x2.f32 %0, %1, %2;" : "=r"(r) : "f"(hi), "f"(lo)); return r;
}
__device__ __forceinline__ float bf_lo(unsigned u) { return __uint_as_float(u << 16); }
__device__ __forceinline__ float bf_hi(unsigned u) { return __uint_as_float(u & 0xFFFF0000u); }

__device__ __forceinline__ void mma16(float4& c, unsigned a0, unsigned a1, unsigned a2, unsigned a3,
                                      unsigned b0, unsigned b1) {
    asm volatile(
        "mma.sync.aligned.m16n8k16.row.col.f32.bf16.bf16.f32 "
        "{%0,%1,%2,%3}, {%4,%5,%6,%7}, {%8,%9}, {%0,%1,%2,%3};"
        : "+f"(c.x), "+f"(c.y), "+f"(c.z), "+f"(c.w)
        : "r"(a0), "r"(a1), "r"(a2), "r"(a3), "r"(b0), "r"(b1));
}
__device__ __forceinline__ unsigned sptr(const void* p) {
    return (unsigned)__cvta_generic_to_shared(p);
}
__device__ __forceinline__ void ldsm_x4(unsigned* r, unsigned addr) {
    asm volatile("ldmatrix.sync.aligned.m8n8.x4.shared.b16 {%0,%1,%2,%3}, [%4];"
        : "=r"(r[0]), "=r"(r[1]), "=r"(r[2]), "=r"(r[3]) : "r"(addr));
}
__device__ __forceinline__ void ldsm_x2(unsigned& r0, unsigned& r1, unsigned addr) {
    asm volatile("ldmatrix.sync.aligned.m8n8.x2.shared.b16 {%0,%1}, [%2];"
        : "=r"(r0), "=r"(r1) : "r"(addr));
}

// -------- scratch (allocation-free: device globals) --------
__device__ bf16 g_h [MTOK*CD];
__device__ bf16 g_q [CB*CH*CS*CHD];      // [bh][S][hd]
__device__ bf16 g_k [CB*CH*CS*CHD];      // [bh][S][hd]
__device__ bf16 g_v [CB*CH*CS*CHD];      // [bh][hd][S]  (pre-transposed, mode 5)
__device__ bf16 g_p [CH*CP*CHD];         // [H][P][hd]
__device__ bf16 g_ao[MTOK*CD];           // [B,S,D]

// ============================ LayerNorm (fp32 in -> bf16 out) ============================
__global__ void __launch_bounds__(128) ln_kernel(const float* __restrict__ x,
    const float* __restrict__ w, const float* __restrict__ b, bf16* __restrict__ out)
{
    int row = blockIdx.x;
    int t = threadIdx.x;
    const float* xr = x + (size_t)row * CD;
    float4 v = *(const float4*)(xr + t * 4);
    float s = v.x + v.y + v.z + v.w;
    #pragma unroll
    for (int o = 16; o; o >>= 1) s += __shfl_xor_sync(0xffffffffu, s, o);
    __shared__ float ws1[4], ws2[4];
    if ((t & 31) == 0) ws1[t >> 5] = s;
    __syncthreads();
    float mean = (ws1[0] + ws1[1] + ws1[2] + ws1[3]) * (1.0f / 512.0f);
    float dx = v.x - mean, dy = v.y - mean, dz = v.z - mean, dw = v.w - mean;
    float q = dx*dx + dy*dy + dz*dz + dw*dw;
    #pragma unroll
    for (int o = 16; o; o >>= 1) q += __shfl_xor_sync(0xffffffffu, q, o);
    if ((t & 31) == 0) ws2[t >> 5] = q;
    __syncthreads();
    float var = (ws2[0] + ws2[1] + ws2[2] + ws2[3]) * (1.0f / 512.0f);
    float rstd = rsqrtf(var + 1e-5f);
    float4 wv = *(const float4*)(w + t * 4);
    float4 bv = *(const float4*)(b + t * 4);
    float ox = dx * rstd * wv.x + bv.x;
    float oy = dy * rstd * wv.y + bv.y;
    float oz = dz * rstd * wv.z + bv.z;
    float ow = dw * rstd * wv.w + bv.w;
    *(uint2*)(out + (size_t)row * CD + t * 4) = make_uint2(pack_bf2(ox, oy), pack_bf2(oz, ow));
}

// ============================ GEMM core: C = A @ W^T (bf16 mma + ldmatrix) ============================
__device__ __forceinline__ void gemm_core(
    const void* __restrict__ Ap, int M, int a_bf16,
    const float* __restrict__ W,
    const float* __restrict__ bias,
    const float* __restrict__ resid,
    void* __restrict__ outp, int mode,
    bf16* As, bf16* Ws)
{
    const int tid = threadIdx.x;
    const int l = tid & 31, wid = tid >> 5;
    const int wm = wid >> 1, wn = wid & 1;
    const int m0 = blockIdx.y * 128, n0 = blockIdx.x * 128;
    const int gid = l >> 2, tig = l & 3;
    const int lr = l & 7;
    const int a_row = ((l >> 3) & 1) * 8 + lr;
    const int a_col = (l >> 4) * 8;
    const int b_col = ((l >> 3) & 1) * 8;

    float4 cacc[2][8];
    #pragma unroll
    for (int mt = 0; mt < 2; mt++)
        #pragma unroll
        for (int nt = 0; nt < 8; nt++) cacc[mt][nt] = make_float4(0.f, 0.f, 0.f, 0.f);

    const unsigned aA = sptr(As) + ((wm * 32 + a_row) * 72 + a_col) * 2;
    const unsigned aB = sptr(Ws) + ((wn * 64 + lr) * 72 + b_col) * 2;

    for (int k0 = 0; k0 < 512; k0 += 64) {
        __syncthreads();
        #pragma unroll
        for (int it = 0; it < 4; it++) {
            int idx = tid + it * 256;
            int row = idx >> 3, seg = idx & 7;
            int kk = k0 + seg * 8;
            int am = m0 + row;
            uint4 aw = make_uint4(0, 0, 0, 0);
            if (am < M) {
                if (a_bf16) {
                    aw = *(const uint4*)((const bf16*)Ap + (size_t)am * 512 + kk);
                } else {
                    const float* ar = (const float*)Ap + (size_t)am * 512 + kk;
                    float4 f0 = *(const float4*)ar;
                    float4 f1 = *(const float4*)(ar + 4);
                    aw = make_uint4(pack_bf2(f0.x, f0.y), pack_bf2(f0.z, f0.w),
                                    pack_bf2(f1.x, f1.y), pack_bf2(f1.z, f1.w));
                }
            }
            *(uint4*)&As[row * 72 + seg * 8] = aw;
            const float* wr = W + (size_t)(n0 + row) * 512 + kk;
            float4 w0 = *(const float4*)wr;
            float4 w1 = *(const float4*)(wr + 4);
            *(uint4*)&Ws[row * 72 + seg * 8] =
                make_uint4(pack_bf2(w0.x, w0.y), pack_bf2(w0.z, w0.w),
                           pack_bf2(w1.x, w1.y), pack_bf2(w1.z, w1.w));
        }
        __syncthreads();
        #pragma unroll
        for (int ks = 0; ks < 4; ks++) {
            unsigned a0[4], a1[4];
            ldsm_x4(a0, aA + ks * 32);
            ldsm_x4(a1, aA + 16 * 144 + ks * 32);
            #pragma unroll
            for (int nt = 0; nt < 8; nt++) {
                unsigned b0, b1;
                ldsm_x2(b0, b1, aB + nt * 8 * 144 + ks * 32);
                mma16(cacc[0][nt], a0[0], a0[1], a0[2], a0[3], b0, b1);
                mma16(cacc[1][nt], a1[0], a1[1], a1[2], a1[3], b0, b1);
            }
        }
    }

    #pragma unroll
    for (int mt = 0; mt < 2; mt++) {
        #pragma unroll
        for (int nt = 0; nt < 8; nt++) {
            float4 c = cacc[mt][nt];
            int r0 = m0 + wm * 32 + mt * 16 + gid;
            int c0 = n0 + wn * 64 + nt * 8 + tig * 2;
            float vals[4] = {c.x, c.y, c.z, c.w};
            #pragma unroll
            for (int e = 0; e < 4; e++) {
                int m = r0 + (e >= 2 ? 8 : 0);
                int n = c0 + (e & 1);
                float val = vals[e];
                if (mode == 0) {
                    int bi = m >> 10, sr = m & 1023;
                    ((bf16*)outp)[((size_t)(bi * CH + (n >> 6)) << 16) + ((size_t)sr << 6) + (n & 63)]
                        = __float2bfloat16(val + bias[n]);
                } else if (mode == 5) {
                    int bi = m >> 10, sr = m & 1023;
                    ((bf16*)outp)[((size_t)(bi * CH + (n >> 6)) << 16) + (size_t)(n & 63) * 1024 + sr]
                        = __float2bfloat16(val + bias[n]);
                } else if (mode == 3) {
                    if (m < M)
                        ((bf16*)outp)[((size_t)(n >> 6) * CP + m) * 64 + (n & 63)]
                            = __float2bfloat16(val);
                } else {
                    size_t idx = (size_t)m * 512 + n;
                    ((float*)outp)[idx] = val + bias[n] + resid[idx];
                }
            }
        }
    }
}

__global__ void __launch_bounds__(256, 2) gemm_kernel(
    const void* __restrict__ Ap, int M, int a_bf16,
    const float* __restrict__ W, const float* __restrict__ bias,
    const float* __restrict__ resid, void* __restrict__ outp, int mode)
{
    __shared__ bf16 As[128 * 72];
    __shared__ bf16 Ws[128 * 72];
    gemm_core(Ap, M, a_bf16, W, bias, resid, outp, mode, As, Ws);
}

__global__ void __launch_bounds__(256, 2) qkv_kernel(
    const bf16* __restrict__ A,
    const float* __restrict__ Wq, const float* __restrict__ Wk, const float* __restrict__ Wv,
    const float* __restrict__ bq, const float* __restrict__ bk, const float* __restrict__ bv,
    bf16* __restrict__ q, bf16* __restrict__ k, bf16* __restrict__ v)
{
    __shared__ bf16 As[128 * 72];
    __shared__ bf16 Ws[128 * 72];
    int z = blockIdx.z;
    const float* W    = (z == 0) ? Wq : (z == 1) ? Wk : Wv;
    const float* bias = (z == 0) ? bq : (z == 1) ? bk : bv;
    bf16* o           = (z == 0) ? q  : (z == 1) ? k  : v;
    gemm_core(A, MTOK, 1, W, bias, nullptr, o, (z == 2) ? 5 : 0, As, Ws);
}

// ============================ Fused attention (bf16 scores, 2 CTAs/SM) ============================
constexpr int SCH    = 1096;                   // bf16 score stride (137*16B rows: ldsm conflict-free)
constexpr int SC_E   = 32 * SCH;               // 35072 bf16
constexpr int QT_E   = 32 * 72;                // 2304 bf16 each
constexpr int KB_E   = 128 * 72;               // 9216 bf16 (Vt 64*136=8704 fits)
constexpr int ASM_B  = (SC_E + 2 * QT_E + KB_E) * 2;   // 97,792 bytes -> 2 CTAs/SM

__global__ void __launch_bounds__(256, 2) attn_kernel(const float* __restrict__ bu,
    const float* __restrict__ bvp, bf16* __restrict__ ao)
{
    extern __shared__ bf16 smb[];
    bf16* sc   = smb;                  // [32][1096] bf16 scores/probs (fp32 partial overlay later)
    bf16* qut  = smb + SC_E;           // [32][72]
    bf16* qvt  = qut + QT_E;           // [32][72]
    bf16* kbuf = qvt + QT_E;           // [128][72] K/P chunk; Vt [64][136]

    const int tid = threadIdx.x;
    const int w = tid >> 5, l = tid & 31;
    const int gid = l >> 2, tig = l & 3;
    const int lr = l & 7;
    const int a_row = ((l >> 3) & 1) * 8 + lr;
    const int a_col = (l >> 4) * 8;
    const int b_col = ((l >> 3) & 1) * 8;
    const int qt = blockIdx.x & 31;
    const int bh = blockIdx.x >> 5;
    const int h  = bh & 7, b = bh >> 3;
    const int i0 = qt * 32;
    const bf16* qbase = g_q + (size_t)bh * (CS * CHD);
    const bf16* kbase = g_k + (size_t)bh * (CS * CHD);
    const bf16* vbase = g_v + (size_t)bh * (CS * CHD);   // [64][1024]
    const bf16* pbase = g_p + (size_t)h  * (CP * CHD);

    // ---- Phase A: q tile [32][72] bf16, both bias variants ----
    {
        int ii = tid >> 3, dq = (tid & 7) * 8;
        uint4 qw = *(const uint4*)(qbase + (size_t)(i0 + ii) * 64 + dq);
        unsigned wsv[4] = {qw.x, qw.y, qw.z, qw.w};
        unsigned uo[4], vo[4];
        #pragma unroll
        for (int j = 0; j < 4; j++) {
            float fx = bf_lo(wsv[j]), fy = bf_hi(wsv[j]);
            int d = dq + 2 * j;
            uo[j] = pack_bf2(fx + bu [h*64+d], fy + bu [h*64+d+1]);
            vo[j] = pack_bf2(fx + bvp[h*64+d], fy + bvp[h*64+d+1]);
        }
        *(uint4*)&qut[ii * 72 + dq] = make_uint4(uo[0], uo[1], uo[2], uo[3]);
        *(uint4*)&qvt[ii * 72 + dq] = make_uint4(vo[0], vo[1], vo[2], vo[3]);
    }

    const unsigned aQU = sptr(qut) + (a_row * 72 + a_col) * 2;
    const unsigned aQV = sptr(qvt) + (a_row * 72 + a_col) * 2;
    const unsigned aKB = sptr(kbuf) + ((w * 16 + lr) * 72 + b_col) * 2;
    const int rlo = 992 - i0;

    // ======== Phase B1: pos scores over band (9 chunks of 128), sheared assign ========
    #pragma unroll 1
    for (int ch = 0; ch < 9; ch++) {
        int rbase = rlo + ch * 128;
        __syncthreads();
        #pragma unroll
        for (int it = 0; it < 4; it++) {
            int idx = tid + it * 256;
            int row = idx >> 3, seg = idx & 7;
            int r = rbase + row;
            uint4 v = (r <= 2046) ? *(const uint4*)(pbase + (size_t)r * 64 + seg * 8)
                                  : make_uint4(0, 0, 0, 0);
            *(uint4*)&kbuf[row * 72 + seg * 8] = v;
        }
        __syncthreads();
        float4 cacc[2][2];
        #pragma unroll
        for (int mt = 0; mt < 2; mt++)
            #pragma unroll
            for (int nt = 0; nt < 2; nt++) cacc[mt][nt] = make_float4(0.f,0.f,0.f,0.f);
        #pragma unroll
        for (int ks = 0; ks < 4; ks++) {
            unsigned a0[4], a1[4];
            ldsm_x4(a0, aQV + ks * 32);
            ldsm_x4(a1, aQV + 16 * 144 + ks * 32);
            #pragma unroll
            for (int nt = 0; nt < 2; nt++) {
                unsigned b0, b1;
                ldsm_x2(b0, b1, aKB + nt * 8 * 144 + ks * 32);
                mma16(cacc[0][nt], a0[0], a0[1], a0[2], a0[3], b0, b1);
                mma16(cacc[1][nt], a1[0], a1[1], a1[2], a1[3], b0, b1);
            }
        }
        #pragma unroll
        for (int mt = 0; mt < 2; mt++) {
            #pragma unroll
            for (int nt = 0; nt < 2; nt++) {
                float4 c = cacc[mt][nt];
                int ii = mt * 16 + gid;
                int rr = ch * 128 + w * 16 + nt * 8 + tig * 2;
                int jx = rr + ii - 31;
                if (jx >= 0 && jx < 1024)         sc[ii * SCH + jx]     = __float2bfloat16(c.x);
                if (jx + 1 >= 0 && jx + 1 < 1024) sc[ii * SCH + jx + 1] = __float2bfloat16(c.y);
                int jz = jx + 8, i2 = ii + 8;
                if (jz >= 0 && jz < 1024)         sc[i2 * SCH + jz]     = __float2bfloat16(c.z);
                if (jz + 1 >= 0 && jz + 1 < 1024) sc[i2 * SCH + jz + 1] = __float2bfloat16(c.w);
            }
        }
    }

    // ======== Phase B2: content scores (8 chunks of 128), add in place (bf16 RMW) ========
    #pragma unroll 1
    for (int ch = 0; ch < 8; ch++) {
        __syncthreads();
        #pragma unroll
        for (int it = 0; it < 4; it++) {
            int idx = tid + it * 256;
            int row = idx >> 3, seg = idx & 7;
            *(uint4*)&kbuf[row * 72 + seg * 8] =
                *(const uint4*)(kbase + (size_t)(ch * 128 + row) * 64 + seg * 8);
        }
        __syncthreads();
        float4 cacc[2][2];
        #pragma unroll
        for (int mt = 0; mt < 2; mt++)
            #pragma unroll
            for (int nt = 0; nt < 2; nt++) cacc[mt][nt] = make_float4(0.f,0.f,0.f,0.f);
        #pragma unroll
        for (int ks = 0; ks < 4; ks++) {
            unsigned a0[4], a1[4];
            ldsm_x4(a0, aQU + ks * 32);
            ldsm_x4(a1, aQU + 16 * 144 + ks * 32);
            #pragma unroll
            for (int nt = 0; nt < 2; nt++) {
                unsigned b0, b1;
                ldsm_x2(b0, b1, aKB + nt * 8 * 144 + ks * 32);
                mma16(cacc[0][nt], a0[0], a0[1], a0[2], a0[3], b0, b1);
                mma16(cacc[1][nt], a1[0], a1[1], a1[2], a1[3], b0, b1);
            }
        }
        #pragma unroll
        for (int mt = 0; mt < 2; mt++) {
            #pragma unroll
            for (int nt = 0; nt < 2; nt++) {
                float4 c = cacc[mt][nt];
                int ii = mt * 16 + gid;
                int col = ch * 128 + w * 16 + nt * 8 + tig * 2;
                unsigned* p0 = (unsigned*)&sc[ii * SCH + col];
                unsigned u0 = *p0;
                *p0 = pack_bf2(bf_lo(u0) + c.x, bf_hi(u0) + c.y);
                unsigned* p1 = (unsigned*)&sc[(ii + 8) * SCH + col];
                unsigned u1 = *p1;
                *p1 = pack_bf2(bf_lo(u1) + c.z, bf_hi(u1) + c.w);
            }
        }
    }
    __syncthreads();

    // ======== Phase C: softmax (scale 1/8 inside exp), 4 rows per warp ========
    #pragma unroll
    for (int rr = 0; rr < 4; rr++) {
        int row = w * 4 + rr;
        bf16* rp = sc + row * SCH;
        unsigned u[16];
        float f[32];
        #pragma unroll
        for (int g = 0; g < 4; g++) {
            uint4 q4 = *(const uint4*)(rp + g * 256 + l * 8);
            u[g*4+0] = q4.x; u[g*4+1] = q4.y; u[g*4+2] = q4.z; u[g*4+3] = q4.w;
        }
        float mx = -1e30f;
        #pragma unroll
        for (int e = 0; e < 16; e++) {
            f[2*e]   = bf_lo(u[e]);
            f[2*e+1] = bf_hi(u[e]);
            mx = fmaxf(mx, fmaxf(f[2*e], f[2*e+1]));
        }
        #pragma unroll
        for (int o = 16; o; o >>= 1) mx = fmaxf(mx, __shfl_xor_sync(0xffffffffu, mx, o));
        float sum = 0.f;
        #pragma unroll
        for (int e = 0; e < 32; e++) {
            f[e] = __expf((f[e] - mx) * 0.125f);
            sum += f[e];
        }
        #pragma unroll
        for (int o = 16; o; o >>= 1) sum += __shfl_xor_sync(0xffffffffu, sum, o);
        float inv = 1.0f / sum;
        #pragma unroll
        for (int g = 0; g < 4; g++) {
            uint4 q4;
            q4.x = pack_bf2(f[g*8+0] * inv, f[g*8+1] * inv);
            q4.y = pack_bf2(f[g*8+2] * inv, f[g*8+3] * inv);
            q4.z = pack_bf2(f[g*8+4] * inv, f[g*8+5] * inv);
            q4.w = pack_bf2(f[g*8+6] * inv, f[g*8+7] * inv);
            *(uint4*)(rp + g * 256 + l * 8) = q4;
        }
    }

    // ======== Phase D: O = attn @ V (8 chunks of 128 keys), 8-way k-split ========
    bf16* Vt = kbuf;                                   // [64][136]
    float4 oacc[2][8];
    #pragma unroll
    for (int mt = 0; mt < 2; mt++)
        #pragma unroll
        for (int nt = 0; nt < 8; nt++) oacc[mt][nt] = make_float4(0.f,0.f,0.f,0.f);

    #pragma unroll 1
    for (int ch = 0; ch < 8; ch++) {
        __syncthreads();
        #pragma unroll
        for (int it = 0; it < 4; it++) {
            int idx = tid + it * 256;
            int d = idx >> 4, seg = idx & 15;
            *(uint4*)&Vt[d * 136 + seg * 8] =
                *(const uint4*)(vbase + (size_t)d * 1024 + ch * 128 + seg * 8);
        }
        __syncthreads();
        // A fragments straight from bf16 prob tile via ldmatrix
        unsigned a0[4], a1[4];
        ldsm_x4(a0, sptr(sc) + (a_row * SCH + ch * 128 + w * 16 + a_col) * 2);
        ldsm_x4(a1, sptr(sc) + ((16 + a_row) * SCH + ch * 128 + w * 16 + a_col) * 2);
        #pragma unroll
        for (int nt = 0; nt < 8; nt++) {
            unsigned b0, b1;
            ldsm_x2(b0, b1, sptr(Vt) + ((nt * 8 + lr) * 136 + w * 16 + b_col) * 2);
            mma16(oacc[0][nt], a0[0], a0[1], a0[2], a0[3], b0, b1);
            mma16(oacc[1][nt], a1[0], a1[1], a1[2], a1[3], b0, b1);
        }
    }

    // per-warp partials -> fp32 overlay over sc (probs dead), then cross-warp reduce
    __syncthreads();
    float* ovl = (float*)sc;
    {
        float* pb = ovl + w * 2176;
        #pragma unroll
        for (int mt = 0; mt < 2; mt++) {
            #pragma unroll
            for (int nt = 0; nt < 8; nt++) {
                float4 c = oacc[mt][nt];
                int r = mt * 16 + gid;
                int cc = nt * 8 + tig * 2;
                pb[r * 68 + cc]           = c.x;
                pb[r * 68 + cc + 1]       = c.y;
                pb[(r + 8) * 68 + cc]     = c.z;
                pb[(r + 8) * 68 + cc + 1] = c.w;
            }
        }
    }
    __syncthreads();
    #pragma unroll
    for (int rep = 0; rep < 2; rep++) {
        int e = tid + rep * 256;
        int row = e >> 4, d4 = (e & 15) * 4;
        float4 s = make_float4(0.f, 0.f, 0.f, 0.f);
        #pragma unroll
        for (int ww = 0; ww < 8; ww++) {
            float4 p4 = *(const float4*)&ovl[ww * 2176 + row * 68 + d4];
            s.x += p4.x; s.y += p4.y; s.z += p4.z; s.w += p4.w;
        }
        *(uint2*)(ao + (size_t)(b * 1024 + i0 + row) * 512 + h * 64 + d4)
            = make_uint2(pack_bf2(s.x, s.y), pack_bf2(s.z, s.w));
    }
}

// ============================ launch ============================
extern "C" void kernel_launch(void* const* d_in, const int* in_sizes, int n_in,
                              void* d_out, int out_size)
{
    const float* x       = (const float*)d_in[0];
    const float* pos_emb = (const float*)d_in[1];
    const float* ln_w    = (const float*)d_in[2];
    const float* ln_b    = (const float*)d_in[3];
    const float* Wq      = (const float*)d_in[4];
    const float* bq      = (const float*)d_in[5];
    const float* Wk      = (const float*)d_in[6];
    const float* bk      = (const float*)d_in[7];
    const float* Wv      = (const float*)d_in[8];
    const float* bv      = (const float*)d_in[9];
    const float* Wo      = (const float*)d_in[10];
    const float* bo      = (const float*)d_in[11];
    const float* Wp      = (const float*)d_in[12];
    const float* pbu     = (const float*)d_in[13];
    const float* pbv     = (const float*)d_in[14];
    float* out = (float*)d_out;

    bf16 *hp, *qp, *kp, *vp, *pp, *aop;
    cudaGetSymbolAddress((void**)&hp,  g_h);
    cudaGetSymbolAddress((void**)&qp,  g_q);
    cudaGetSymbolAddress((void**)&kp,  g_k);
    cudaGetSymbolAddress((void**)&vp,  g_v);
    cudaGetSymbolAddress((void**)&pp,  g_p);
    cudaGetSymbolAddress((void**)&aop, g_ao);

    cudaFuncSetAttribute(attn_kernel, cudaFuncAttributeMaxDynamicSharedMemorySize, ASM_B);

    ln_kernel<<<MTOK, 128>>>(x, ln_w, ln_b, hp);

    qkv_kernel<<<dim3(4, 64, 3), 256>>>(hp, Wq, Wk, Wv, bq, bk, bv, qp, kp, vp);
    gemm_kernel<<<dim3(4, 16), 256>>>(pos_emb, CP, 0, Wp, nullptr, nullptr, pp, 3);

    attn_kernel<<<CB * CH * (CS / 32), 256, ASM_B>>>(pbu, pbv, aop);

    gemm_kernel<<<dim3(4, 64), 256>>>(aop, MTOK, 1, Wo, bo, x, out, 4);
}